// round 12
// baseline (speedup 1.0000x reference)
#include <cuda_runtime.h>
#include <math.h>

#define BATCH 128
#define SEQ 48
#define FEAT 60
#define NH 5
#define NV 6
#define TWO_PI 6.2831853071795864769f
#define SQRT_HALF 0.70710678118654752440f

struct C2 { float re, im; };
struct M2 { C2 m00, m01, m10, m11; };

__device__ __forceinline__ C2 cmul(C2 a, C2 b) {
    C2 r; r.re = a.re*b.re - a.im*b.im; r.im = a.re*b.im + a.im*b.re; return r;
}
__device__ __forceinline__ C2 cadd(C2 a, C2 b) { C2 r{a.re+b.re, a.im+b.im}; return r; }

// U = RZ(t3) * RY(t2) * RX(t1)
__device__ __forceinline__ M2 fuse_zyx(float t1, float t2, float t3) {
    float c1,s1,c2,s2,c3,s3;
    sincosf(0.5f*t1, &s1, &c1);
    sincosf(0.5f*t2, &s2, &c2);
    sincosf(0.5f*t3, &s3, &c3);
    C2 a00{c1,0.f}, a01{0.f,-s1}, a10{0.f,-s1}, a11{c1,0.f};
    C2 m00{c2*a00.re - s2*a10.re, c2*a00.im - s2*a10.im};
    C2 m01{c2*a01.re - s2*a11.re, c2*a01.im - s2*a11.im};
    C2 m10{s2*a00.re + c2*a10.re, s2*a00.im + c2*a10.im};
    C2 m11{s2*a01.re + c2*a11.re, s2*a01.im + c2*a11.im};
    C2 r0{c3,-s3}, r1{c3,s3};
    M2 u;
    u.m00 = cmul(r0,m00); u.m01 = cmul(r0,m01);
    u.m10 = cmul(r1,m10); u.m11 = cmul(r1,m11);
    return u;
}
__device__ __forceinline__ M2 mmul(M2 p, M2 q) {
    M2 r;
    r.m00 = cadd(cmul(p.m00,q.m00), cmul(p.m01,q.m10));
    r.m01 = cadd(cmul(p.m00,q.m01), cmul(p.m01,q.m11));
    r.m10 = cadd(cmul(p.m10,q.m00), cmul(p.m11,q.m10));
    r.m11 = cadd(cmul(p.m10,q.m01), cmul(p.m11,q.m11));
    return r;
}

// ---- cooperative SMEM gate stages: state S[amp][col], stride 33 ----
template<int M>
__device__ __forceinline__ void g1q_s(float* Sre, float* Sim, int col, int w, const M2& g) {
    #pragma unroll
    for (int pp = 0; pp < 4; ++pp) {
        int p = 4*w + pp;
        int i = ((p & ~(M-1)) << 1) | (p & (M-1));
        int j = i | M;
        float ar = Sre[i*33+col], ai = Sim[i*33+col];
        float br = Sre[j*33+col], bi = Sim[j*33+col];
        Sre[i*33+col] = g.m00.re*ar - g.m00.im*ai + g.m01.re*br - g.m01.im*bi;
        Sim[i*33+col] = g.m00.re*ai + g.m00.im*ar + g.m01.re*bi + g.m01.im*br;
        Sre[j*33+col] = g.m10.re*ar - g.m10.im*ai + g.m11.re*br - g.m11.im*bi;
        Sim[j*33+col] = g.m10.re*ai + g.m10.im*ar + g.m11.re*bi + g.m11.im*br;
    }
}
template<int MC, int MT>
__device__ __forceinline__ void gcrx_s(float* Sre, float* Sim, int col, int w, float c, float s) {
    #pragma unroll
    for (int pp = 0; pp < 2; ++pp) {
        int p = 2*w + pp;
        int i = ((p & ~(MT-1)) << 2) | MC | (p & (MT-1));
        int j = i | MT;
        float a0r = Sre[i*33+col], a0i = Sim[i*33+col];
        float a1r = Sre[j*33+col], a1i = Sim[j*33+col];
        Sre[i*33+col] = c*a0r + s*a1i;
        Sim[i*33+col] = c*a0i - s*a1r;
        Sre[j*33+col] = s*a0i + c*a1r;
        Sim[j*33+col] = c*a1i - s*a0r;
    }
}

__global__ __launch_bounds__(128)
void qrnn_kernel(const float* __restrict__ x,
                 const float* __restrict__ hidden,
                 const float* __restrict__ params,
                 float* __restrict__ out)
{
    const int b   = blockIdx.x;
    const int tid = threadIdx.x;
    const int col = tid & 31;
    const int w   = tid >> 5;

    __shared__ float Sre[32*33];
    __shared__ float Sim[32*33];

    // ======== cooperative precompute of U'' = CRX1*G2*CRX0*G1 (all 128 threads) ========
    {
        M2 h1[5], h2[5];
        #pragma unroll
        for (int q = 0; q < 5; q++) {
            h1[q] = fuse_zyx(params[3*q],    params[3*q+1],    params[3*q+2]);
            h2[q] = fuse_zyx(params[37+3*q], params[37+3*q+1], params[37+3*q+2]);
        }
        float cx[8], sx[8];
        #pragma unroll
        for (int k = 0; k < 8; k++) {
            int l = k >> 2, kk = k & 3;
            sincosf(0.5f*params[l*37 + 15 + kk], &sx[k], &cx[k]);
        }

        #pragma unroll
        for (int r = 0; r < 8; ++r) {
            int i = 8*w + r;
            Sre[i*33 + col] = (i == col) ? 1.f : 0.f;
            Sim[i*33 + col] = 0.f;
        }
        __syncthreads();

        g1q_s<16>(Sre, Sim, col, w, h1[0]); __syncthreads();
        g1q_s< 8>(Sre, Sim, col, w, h1[1]); __syncthreads();
        g1q_s< 4>(Sre, Sim, col, w, h1[2]); __syncthreads();
        g1q_s< 2>(Sre, Sim, col, w, h1[3]); __syncthreads();
        g1q_s< 1>(Sre, Sim, col, w, h1[4]); __syncthreads();
        gcrx_s<16,8>(Sre, Sim, col, w, cx[0], sx[0]); __syncthreads();
        gcrx_s< 8,4>(Sre, Sim, col, w, cx[1], sx[1]); __syncthreads();
        gcrx_s< 4,2>(Sre, Sim, col, w, cx[2], sx[2]); __syncthreads();
        gcrx_s< 2,1>(Sre, Sim, col, w, cx[3], sx[3]); __syncthreads();
        g1q_s<16>(Sre, Sim, col, w, h2[0]); __syncthreads();
        g1q_s< 8>(Sre, Sim, col, w, h2[1]); __syncthreads();
        g1q_s< 4>(Sre, Sim, col, w, h2[2]); __syncthreads();
        g1q_s< 2>(Sre, Sim, col, w, h2[3]); __syncthreads();
        g1q_s< 1>(Sre, Sim, col, w, h2[4]); __syncthreads();
        gcrx_s<16,8>(Sre, Sim, col, w, cx[4], sx[4]); __syncthreads();
        gcrx_s< 8,4>(Sre, Sim, col, w, cx[5], sx[5]); __syncthreads();
        gcrx_s< 4,2>(Sre, Sim, col, w, cx[6], sx[6]); __syncthreads();
        gcrx_s< 2,1>(Sre, Sim, col, w, cx[7], sx[7]); __syncthreads();
    }

    if (tid < 32) {
        // ================= warp 0: hidden recurrence loop (pure scalar FP) =================
        const int lane = tid;
        const bool special = (__popc(lane) == 1) && (lane <= 16);
        const int q_of_lane = special ? (__clz(lane) - 27) : 0;   // lane16->q0 ... lane1->q4

        // read ROW lane of U'', fold embed phase (-i)^popc(col) AND sqrt(1/2) scaling
        float Rr[32], Ri[32];
        #pragma unroll
        for (int j = 0; j < 32; ++j) {
            float re = Sre[lane*33 + j] * SQRT_HALF;
            float im = Sim[lane*33 + j] * SQRT_HALF;
            int k = __popc(j) & 3;
            float a, bb;
            if (k == 0)      { a =  re; bb =  im; }
            else if (k == 1) { a =  im; bb = -re; }
            else if (k == 2) { a = -re; bb = -im; }
            else             { a = -im; bb =  re; }
            Rr[j] = a; Ri[j] = bb;
        }

        // state: zh = z/2 (half-angle form)
        float zh = special ? 0.5f*hidden[b*NH + q_of_lane] : 0.f;

        #pragma unroll 1
        for (int t = 0; t < SEQ; ++t) {
            // ---- sincos(zh) on special lanes; broadcast 5 (c,s) pairs ----
            float cc, ss;
            __sincosf(zh, &ss, &cc);
            float c0 = __shfl_sync(0xffffffffu, cc, 16), s0 = __shfl_sync(0xffffffffu, ss, 16);
            float c1 = __shfl_sync(0xffffffffu, cc,  8), s1 = __shfl_sync(0xffffffffu, ss,  8);
            float c2 = __shfl_sync(0xffffffffu, cc,  4), s2 = __shfl_sync(0xffffffffu, ss,  4);
            float c3 = __shfl_sync(0xffffffffu, cc,  2), s3 = __shfl_sync(0xffffffffu, ss,  2);
            float c4 = __shfl_sync(0xffffffffu, cc,  1), s4 = __shfl_sync(0xffffffffu, ss,  1);

            // ---- g over qubits 0..2 (8 values), h over qubits 3,4 (4 values) ----
            float g00 = c0*c1, g01 = c0*s1, g10 = s0*c1, g11 = s0*s1;
            float g0 = g00*c2, g1 = g00*s2, g2 = g01*c2, g3 = g01*s2;
            float g4 = g10*c2, g5 = g10*s2, g6 = g11*c2, g7 = g11*s2;
            float h0 = c3*c4, h1 = c3*s4, h2 = s3*c4, h3 = s3*s4;

            // ---- matvec amp = U''·m, m_j = g[j>>2]·h[j&3]; grouped 4-dots ----
            float aR0 = 0.f, aR1 = 0.f, aI0 = 0.f, aI1 = 0.f;
            #define GRP(k, g, accR, accI)                                   \
            {                                                               \
                float t0 = fmaf(Rr[4*(k)+1], h1, Rr[4*(k)  ] * h0);         \
                float t1 = fmaf(Rr[4*(k)+3], h3, Rr[4*(k)+2] * h2);         \
                accR = fmaf(g, t0 + t1, accR);                              \
                float u0 = fmaf(Ri[4*(k)+1], h1, Ri[4*(k)  ] * h0);         \
                float u1 = fmaf(Ri[4*(k)+3], h3, Ri[4*(k)+2] * h2);         \
                accI = fmaf(g, u0 + u1, accI);                              \
            }
            GRP(0, g0, aR0, aI0) GRP(1, g1, aR1, aI1)
            GRP(2, g2, aR0, aI0) GRP(3, g3, aR1, aI1)
            GRP(4, g4, aR0, aI0) GRP(5, g5, aR1, aI1)
            GRP(6, g6, aR0, aI0) GRP(7, g7, aR1, aI1)
            #undef GRP
            float nar = aR0 + aR1;
            float nai = aI0 + aI1;

            // ---- measure: p = |amp|^2 (already x1/2); WHT butterfly -> z_q/2 ----
            float v = fmaf(nar, nar, nai*nai);
            #pragma unroll
            for (int m2 = 16; m2 >= 1; m2 >>= 1) {
                float o = __shfl_xor_sync(0xffffffffu, v, m2);
                v = (lane & m2) ? (o - v) : (v + o);
            }
            zh = v;   // non-special lanes' zh never sourced (shuffle srcs 16/8/4/2/1)
        }
        if (special) out[BATCH*SEQ*NV + b*NH + q_of_lane] = 2.f*zh;

    } else {
        // ============ warps 1-3: closed-form outputs for this batch ============
        const int t = tid - 32;
        if (t >= SEQ) return;

        float Cc[6], Dd[6], Ee[6];
        #pragma unroll
        for (int q = 0; q < 6; q++) {
            M2 u0 = fuse_zyx(params[19+3*q],    params[20+3*q],    params[21+3*q]);
            M2 u1 = fuse_zyx(params[37+19+3*q], params[37+20+3*q], params[37+21+3*q]);
            M2 M = mmul(u1, u0);
            float h00 = (M.m00.re*M.m00.re + M.m00.im*M.m00.im)
                      - (M.m10.re*M.m10.re + M.m10.im*M.m10.im);
            float h11 = (M.m01.re*M.m01.re + M.m01.im*M.m01.im)
                      - (M.m11.re*M.m11.re + M.m11.im*M.m11.im);
            float imh01 = (M.m00.re*M.m01.im - M.m00.im*M.m01.re)
                        - (M.m10.re*M.m11.im - M.m10.im*M.m11.re);
            Cc[q] = 0.5f*(h00 + h11);
            Dd[q] = 0.5f*(h00 - h11);
            Ee[q] = imh01;
        }

        const int P = b * SEQ + t;
        const float4* x4 = (const float4*)(x + (size_t)P * FEAT);
        float vals[60];
        #pragma unroll
        for (int k = 0; k < 15; k++) {
            float4 v4 = x4[k];
            vals[4*k+0] = v4.x; vals[4*k+1] = v4.y;
            vals[4*k+2] = v4.z; vals[4*k+3] = v4.w;
        }
        float pooled[6];
        #pragma unroll
        for (int v = 0; v < 6; v++) {
            float s = 0.f;
            #pragma unroll
            for (int j = 0; j < 10; j++) s += vals[v*10 + j];
            pooled[v] = 0.1f * s;
        }
        float mn = pooled[0], mx = pooled[0];
        #pragma unroll
        for (int v = 1; v < 6; v++) {
            mn = fminf(mn, pooled[v]);
            mx = fmaxf(mx, pooled[v]);
        }
        float scale = TWO_PI / (mx - mn + 1e-8f);
        #pragma unroll
        for (int v = 0; v < 6; v++) {
            float a = scale * (pooled[v] - mn);
            float sa, ca;
            sincosf(a, &sa, &ca);
            out[(size_t)P*6 + v] = Cc[v] + Dd[v]*ca + Ee[v]*sa;
        }
    }
}

extern "C" void kernel_launch(void* const* d_in, const int* in_sizes, int n_in,
                              void* d_out, int out_size) {
    const float* x      = (const float*)d_in[0];
    const float* hidden = (const float*)d_in[1];
    const float* params = (const float*)d_in[2];
    float* out = (float*)d_out;
    qrnn_kernel<<<BATCH, 128>>>(x, hidden, params, out);
}

// round 13
// speedup vs baseline: 1.0259x; 1.0259x over previous
#include <cuda_runtime.h>
#include <math.h>

#define BATCH 128
#define SEQ 48
#define FEAT 60
#define NH 5
#define NV 6
#define TWO_PI 6.2831853071795864769f

struct C2 { float re, im; };
struct M2 { C2 m00, m01, m10, m11; };

__device__ __forceinline__ C2 cmul(C2 a, C2 b) {
    C2 r; r.re = a.re*b.re - a.im*b.im; r.im = a.re*b.im + a.im*b.re; return r;
}
__device__ __forceinline__ C2 cadd(C2 a, C2 b) { C2 r{a.re+b.re, a.im+b.im}; return r; }

// U = RZ(t3) * RY(t2) * RX(t1)
__device__ __forceinline__ M2 fuse_zyx(float t1, float t2, float t3) {
    float c1,s1,c2,s2,c3,s3;
    sincosf(0.5f*t1, &s1, &c1);
    sincosf(0.5f*t2, &s2, &c2);
    sincosf(0.5f*t3, &s3, &c3);
    C2 a00{c1,0.f}, a01{0.f,-s1}, a10{0.f,-s1}, a11{c1,0.f};
    C2 m00{c2*a00.re - s2*a10.re, c2*a00.im - s2*a10.im};
    C2 m01{c2*a01.re - s2*a11.re, c2*a01.im - s2*a11.im};
    C2 m10{s2*a00.re + c2*a10.re, s2*a00.im + c2*a10.im};
    C2 m11{s2*a01.re + c2*a11.re, s2*a01.im + c2*a11.im};
    C2 r0{c3,-s3}, r1{c3,s3};
    M2 u;
    u.m00 = cmul(r0,m00); u.m01 = cmul(r0,m01);
    u.m10 = cmul(r1,m10); u.m11 = cmul(r1,m11);
    return u;
}
__device__ __forceinline__ M2 mmul(M2 p, M2 q) {
    M2 r;
    r.m00 = cadd(cmul(p.m00,q.m00), cmul(p.m01,q.m10));
    r.m01 = cadd(cmul(p.m00,q.m01), cmul(p.m01,q.m11));
    r.m10 = cadd(cmul(p.m10,q.m00), cmul(p.m11,q.m10));
    r.m11 = cadd(cmul(p.m10,q.m01), cmul(p.m11,q.m11));
    return r;
}

// ---- cooperative SMEM gate stages: state S[amp][col], stride 33 ----
template<int M>
__device__ __forceinline__ void g1q_s(float* Sre, float* Sim, int col, int w, const M2& g) {
    #pragma unroll
    for (int pp = 0; pp < 4; ++pp) {
        int p = 4*w + pp;
        int i = ((p & ~(M-1)) << 1) | (p & (M-1));
        int j = i | M;
        float ar = Sre[i*33+col], ai = Sim[i*33+col];
        float br = Sre[j*33+col], bi = Sim[j*33+col];
        Sre[i*33+col] = g.m00.re*ar - g.m00.im*ai + g.m01.re*br - g.m01.im*bi;
        Sim[i*33+col] = g.m00.re*ai + g.m00.im*ar + g.m01.re*bi + g.m01.im*br;
        Sre[j*33+col] = g.m10.re*ar - g.m10.im*ai + g.m11.re*br - g.m11.im*bi;
        Sim[j*33+col] = g.m10.re*ai + g.m10.im*ar + g.m11.re*bi + g.m11.im*br;
    }
}
template<int MC, int MT>
__device__ __forceinline__ void gcrx_s(float* Sre, float* Sim, int col, int w, float c, float s) {
    #pragma unroll
    for (int pp = 0; pp < 2; ++pp) {
        int p = 2*w + pp;
        int i = ((p & ~(MT-1)) << 2) | MC | (p & (MT-1));
        int j = i | MT;
        float a0r = Sre[i*33+col], a0i = Sim[i*33+col];
        float a1r = Sre[j*33+col], a1i = Sim[j*33+col];
        Sre[i*33+col] = c*a0r + s*a1i;
        Sim[i*33+col] = c*a0i - s*a1r;
        Sre[j*33+col] = s*a0i + c*a1r;
        Sim[j*33+col] = c*a1i - s*a0r;
    }
}

__global__ __launch_bounds__(128)
void qrnn_kernel(const float* __restrict__ x,
                 const float* __restrict__ hidden,
                 const float* __restrict__ params,
                 float* __restrict__ out)
{
    const int b   = blockIdx.x;
    const int tid = threadIdx.x;
    const int col = tid & 31;
    const int w   = tid >> 5;

    __shared__ float Sre[32*33];
    __shared__ float Sim[32*33];

    // ======== cooperative precompute of U'' = CRX1*G2*CRX0*G1 (all 128 threads) ========
    {
        M2 h1[5], h2[5];
        #pragma unroll
        for (int q = 0; q < 5; q++) {
            h1[q] = fuse_zyx(params[3*q],    params[3*q+1],    params[3*q+2]);
            h2[q] = fuse_zyx(params[37+3*q], params[37+3*q+1], params[37+3*q+2]);
        }
        float cx[8], sx[8];
        #pragma unroll
        for (int k = 0; k < 8; k++) {
            int l = k >> 2, kk = k & 3;
            sincosf(0.5f*params[l*37 + 15 + kk], &sx[k], &cx[k]);
        }

        #pragma unroll
        for (int r = 0; r < 8; ++r) {
            int i = 8*w + r;
            Sre[i*33 + col] = (i == col) ? 1.f : 0.f;
            Sim[i*33 + col] = 0.f;
        }
        __syncthreads();

        g1q_s<16>(Sre, Sim, col, w, h1[0]); __syncthreads();
        g1q_s< 8>(Sre, Sim, col, w, h1[1]); __syncthreads();
        g1q_s< 4>(Sre, Sim, col, w, h1[2]); __syncthreads();
        g1q_s< 2>(Sre, Sim, col, w, h1[3]); __syncthreads();
        g1q_s< 1>(Sre, Sim, col, w, h1[4]); __syncthreads();
        gcrx_s<16,8>(Sre, Sim, col, w, cx[0], sx[0]); __syncthreads();
        gcrx_s< 8,4>(Sre, Sim, col, w, cx[1], sx[1]); __syncthreads();
        gcrx_s< 4,2>(Sre, Sim, col, w, cx[2], sx[2]); __syncthreads();
        gcrx_s< 2,1>(Sre, Sim, col, w, cx[3], sx[3]); __syncthreads();
        g1q_s<16>(Sre, Sim, col, w, h2[0]); __syncthreads();
        g1q_s< 8>(Sre, Sim, col, w, h2[1]); __syncthreads();
        g1q_s< 4>(Sre, Sim, col, w, h2[2]); __syncthreads();
        g1q_s< 2>(Sre, Sim, col, w, h2[3]); __syncthreads();
        g1q_s< 1>(Sre, Sim, col, w, h2[4]); __syncthreads();
        gcrx_s<16,8>(Sre, Sim, col, w, cx[4], sx[4]); __syncthreads();
        gcrx_s< 8,4>(Sre, Sim, col, w, cx[5], sx[5]); __syncthreads();
        gcrx_s< 4,2>(Sre, Sim, col, w, cx[6], sx[6]); __syncthreads();
        gcrx_s< 2,1>(Sre, Sim, col, w, cx[7], sx[7]); __syncthreads();
    }

    if (tid < 32) {
        // ======== warp 0: recurrence loop — ZERO shuffles, 5 REDUX per step ========
        const int lane = tid;

        // read ROW lane of U'', fold embed phase (-i)^popc(col)
        float Rr[32], Ri[32];
        #pragma unroll
        for (int j = 0; j < 32; ++j) {
            float re = Sre[lane*33 + j];
            float im = Sim[lane*33 + j];
            int k = __popc(j) & 3;
            float a, bb;
            if (k == 0)      { a =  re; bb =  im; }
            else if (k == 1) { a =  im; bb = -re; }
            else if (k == 2) { a = -re; bb = -im; }
            else             { a = -im; bb =  re; }
            Rr[j] = a; Ri[j] = bb;
        }

        // half-angles zf_q = z_q/2, replicated on ALL lanes
        float zf0 = 0.5f*hidden[b*NH + 0];
        float zf1 = 0.5f*hidden[b*NH + 1];
        float zf2 = 0.5f*hidden[b*NH + 2];
        float zf3 = 0.5f*hidden[b*NH + 3];
        float zf4 = 0.5f*hidden[b*NH + 4];

        const float SCALE    = 1073741824.0f;          // 2^30
        const float INV2_31  = 4.656612873077393e-10f; // 2^-31  (t*2^-30 * 1/2)

        #pragma unroll 1
        for (int t = 0; t < SEQ; ++t) {
            // ---- local trig of all 5 angles (lane-invariant) ----
            float c0 = __cosf(zf0), s0 = __sinf(zf0);
            float c1 = __cosf(zf1), s1 = __sinf(zf1);
            float c2 = __cosf(zf2), s2 = __sinf(zf2);
            float c3 = __cosf(zf3), s3 = __sinf(zf3);
            float c4 = __cosf(zf4), s4 = __sinf(zf4);

            // ---- g over qubits 0..2 (8), h over qubits 3,4 (4) ----
            float g00 = c0*c1, g01 = c0*s1, g10 = s0*c1, g11 = s0*s1;
            float g0 = g00*c2, g1 = g00*s2, g2 = g01*c2, g3 = g01*s2;
            float g4 = g10*c2, g5 = g10*s2, g6 = g11*c2, g7 = g11*s2;
            float h0 = c3*c4, h1 = c3*s4, h2 = s3*c4, h3 = s3*s4;

            // ---- matvec amp = U''·m, m_j = g[j>>2]·h[j&3]; grouped 4-dots ----
            float aR0 = 0.f, aR1 = 0.f, aI0 = 0.f, aI1 = 0.f;
            #define GRP(k, g, accR, accI)                                   \
            {                                                               \
                float t0 = fmaf(Rr[4*(k)+1], h1, Rr[4*(k)  ] * h0);         \
                float t1 = fmaf(Rr[4*(k)+3], h3, Rr[4*(k)+2] * h2);         \
                accR = fmaf(g, t0 + t1, accR);                              \
                float u0 = fmaf(Ri[4*(k)+1], h1, Ri[4*(k)  ] * h0);         \
                float u1 = fmaf(Ri[4*(k)+3], h3, Ri[4*(k)+2] * h2);         \
                accI = fmaf(g, u0 + u1, accI);                              \
            }
            GRP(0, g0, aR0, aI0) GRP(1, g1, aR1, aI1)
            GRP(2, g2, aR0, aI0) GRP(3, g3, aR1, aI1)
            GRP(4, g4, aR0, aI0) GRP(5, g5, aR1, aI1)
            GRP(6, g6, aR0, aI0) GRP(7, g7, aR1, aI1)
            #undef GRP
            float nar = aR0 + aR1;
            float nai = aI0 + aI1;

            // ---- measure: fixed-point p, 5 REDUX (result on ALL lanes) ----
            float p = fmaf(nar, nar, nai*nai);
            int ip = __float2int_rn(p * SCALE);
            int nip = -ip;
            int t0 = __reduce_add_sync(0xffffffffu, (lane & 16) ? nip : ip);
            int t1 = __reduce_add_sync(0xffffffffu, (lane &  8) ? nip : ip);
            int t2 = __reduce_add_sync(0xffffffffu, (lane &  4) ? nip : ip);
            int t3 = __reduce_add_sync(0xffffffffu, (lane &  2) ? nip : ip);
            int t4 = __reduce_add_sync(0xffffffffu, (lane &  1) ? nip : ip);

            zf0 = (float)t0 * INV2_31;
            zf1 = (float)t1 * INV2_31;
            zf2 = (float)t2 * INV2_31;
            zf3 = (float)t3 * INV2_31;
            zf4 = (float)t4 * INV2_31;
        }

        if (lane < NH) {
            float zz = 2.f*zf0;
            zz = (lane == 1) ? 2.f*zf1 : zz;
            zz = (lane == 2) ? 2.f*zf2 : zz;
            zz = (lane == 3) ? 2.f*zf3 : zz;
            zz = (lane == 4) ? 2.f*zf4 : zz;
            out[BATCH*SEQ*NV + b*NH + lane] = zz;
        }

    } else {
        // ============ warps 1-3: closed-form outputs for this batch ============
        const int t = tid - 32;
        if (t >= SEQ) return;

        float Cc[6], Dd[6], Ee[6];
        #pragma unroll
        for (int q = 0; q < 6; q++) {
            M2 u0 = fuse_zyx(params[19+3*q],    params[20+3*q],    params[21+3*q]);
            M2 u1 = fuse_zyx(params[37+19+3*q], params[37+20+3*q], params[37+21+3*q]);
            M2 M = mmul(u1, u0);
            float h00 = (M.m00.re*M.m00.re + M.m00.im*M.m00.im)
                      - (M.m10.re*M.m10.re + M.m10.im*M.m10.im);
            float h11 = (M.m01.re*M.m01.re + M.m01.im*M.m01.im)
                      - (M.m11.re*M.m11.re + M.m11.im*M.m11.im);
            float imh01 = (M.m00.re*M.m01.im - M.m00.im*M.m01.re)
                        - (M.m10.re*M.m11.im - M.m10.im*M.m11.re);
            Cc[q] = 0.5f*(h00 + h11);
            Dd[q] = 0.5f*(h00 - h11);
            Ee[q] = imh01;
        }

        const int P = b * SEQ + t;
        const float4* x4 = (const float4*)(x + (size_t)P * FEAT);
        float vals[60];
        #pragma unroll
        for (int k = 0; k < 15; k++) {
            float4 v4 = x4[k];
            vals[4*k+0] = v4.x; vals[4*k+1] = v4.y;
            vals[4*k+2] = v4.z; vals[4*k+3] = v4.w;
        }
        float pooled[6];
        #pragma unroll
        for (int v = 0; v < 6; v++) {
            float s = 0.f;
            #pragma unroll
            for (int j = 0; j < 10; j++) s += vals[v*10 + j];
            pooled[v] = 0.1f * s;
        }
        float mn = pooled[0], mx = pooled[0];
        #pragma unroll
        for (int v = 1; v < 6; v++) {
            mn = fminf(mn, pooled[v]);
            mx = fmaxf(mx, pooled[v]);
        }
        float scale = TWO_PI / (mx - mn + 1e-8f);
        #pragma unroll
        for (int v = 0; v < 6; v++) {
            float a = scale * (pooled[v] - mn);
            float sa, ca;
            sincosf(a, &sa, &ca);
            out[(size_t)P*6 + v] = Cc[v] + Dd[v]*ca + Ee[v]*sa;
        }
    }
}

extern "C" void kernel_launch(void* const* d_in, const int* in_sizes, int n_in,
                              void* d_out, int out_size) {
    const float* x      = (const float*)d_in[0];
    const float* hidden = (const float*)d_in[1];
    const float* params = (const float*)d_in[2];
    float* out = (float*)d_out;
    qrnn_kernel<<<BATCH, 128>>>(x, hidden, params, out);
}

// round 14
// speedup vs baseline: 1.4594x; 1.4225x over previous
#include <cuda_runtime.h>
#include <math.h>

#define BATCH 128
#define SEQ 48
#define FEAT 60
#define NH 5
#define NV 6
#define TWO_PI 6.2831853071795864769f

struct C2 { float re, im; };
struct M2 { C2 m00, m01, m10, m11; };

__device__ __forceinline__ C2 cmul(C2 a, C2 b) {
    C2 r; r.re = a.re*b.re - a.im*b.im; r.im = a.re*b.im + a.im*b.re; return r;
}
__device__ __forceinline__ C2 cadd(C2 a, C2 b) { C2 r{a.re+b.re, a.im+b.im}; return r; }

// U = RZ(t3) * RY(t2) * RX(t1)
__device__ __forceinline__ M2 fuse_zyx(float t1, float t2, float t3) {
    float c1,s1,c2,s2,c3,s3;
    sincosf(0.5f*t1, &s1, &c1);
    sincosf(0.5f*t2, &s2, &c2);
    sincosf(0.5f*t3, &s3, &c3);
    C2 a00{c1,0.f}, a01{0.f,-s1}, a10{0.f,-s1}, a11{c1,0.f};
    C2 m00{c2*a00.re - s2*a10.re, c2*a00.im - s2*a10.im};
    C2 m01{c2*a01.re - s2*a11.re, c2*a01.im - s2*a11.im};
    C2 m10{s2*a00.re + c2*a10.re, s2*a00.im + c2*a10.im};
    C2 m11{s2*a01.re + c2*a11.re, s2*a01.im + c2*a11.im};
    C2 r0{c3,-s3}, r1{c3,s3};
    M2 u;
    u.m00 = cmul(r0,m00); u.m01 = cmul(r0,m01);
    u.m10 = cmul(r1,m10); u.m11 = cmul(r1,m11);
    return u;
}
__device__ __forceinline__ M2 mmul(M2 p, M2 q) {
    M2 r;
    r.m00 = cadd(cmul(p.m00,q.m00), cmul(p.m01,q.m10));
    r.m01 = cadd(cmul(p.m00,q.m01), cmul(p.m01,q.m11));
    r.m10 = cadd(cmul(p.m10,q.m00), cmul(p.m11,q.m10));
    r.m11 = cadd(cmul(p.m10,q.m01), cmul(p.m11,q.m11));
    return r;
}

__device__ __forceinline__ M2 load_gate(const float* gm) {
    M2 g;
    g.m00.re = gm[0]; g.m00.im = gm[1];
    g.m01.re = gm[2]; g.m01.im = gm[3];
    g.m10.re = gm[4]; g.m10.im = gm[5];
    g.m11.re = gm[6]; g.m11.im = gm[7];
    return g;
}

// ---- cooperative SMEM gate stages: state S[amp][col], stride 33 ----
template<int M>
__device__ __forceinline__ void g1q_s(float* Sre, float* Sim, int col, int w, const float* gm) {
    M2 g = load_gate(gm);
    #pragma unroll
    for (int pp = 0; pp < 4; ++pp) {
        int p = 4*w + pp;
        int i = ((p & ~(M-1)) << 1) | (p & (M-1));
        int j = i | M;
        float ar = Sre[i*33+col], ai = Sim[i*33+col];
        float br = Sre[j*33+col], bi = Sim[j*33+col];
        Sre[i*33+col] = g.m00.re*ar - g.m00.im*ai + g.m01.re*br - g.m01.im*bi;
        Sim[i*33+col] = g.m00.re*ai + g.m00.im*ar + g.m01.re*bi + g.m01.im*br;
        Sre[j*33+col] = g.m10.re*ar - g.m10.im*ai + g.m11.re*br - g.m11.im*bi;
        Sim[j*33+col] = g.m10.re*ai + g.m10.im*ar + g.m11.re*bi + g.m11.im*br;
    }
}
template<int MC, int MT>
__device__ __forceinline__ void gcrx_s(float* Sre, float* Sim, int col, int w, float c, float s) {
    #pragma unroll
    for (int pp = 0; pp < 2; ++pp) {
        int p = 2*w + pp;
        int i = ((p & ~(MT-1)) << 2) | MC | (p & (MT-1));
        int j = i | MT;
        float a0r = Sre[i*33+col], a0i = Sim[i*33+col];
        float a1r = Sre[j*33+col], a1i = Sim[j*33+col];
        Sre[i*33+col] = c*a0r + s*a1i;
        Sim[i*33+col] = c*a0i - s*a1r;
        Sre[j*33+col] = s*a0i + c*a1r;
        Sim[j*33+col] = c*a1i - s*a0r;
    }
}

__global__ __launch_bounds__(128)
void qrnn_kernel(const float* __restrict__ x,
                 const float* __restrict__ hidden,
                 const float* __restrict__ params,
                 float* __restrict__ out)
{
    const int b   = blockIdx.x;
    const int tid = threadIdx.x;
    const int col = tid & 31;
    const int w   = tid >> 5;

    __shared__ float Sre[32*33];
    __shared__ float Sim[32*33];
    __shared__ float GM[10][8];    // h1[0..4] = GM[0..4], h2[0..4] = GM[5..9]
    __shared__ float CXs[8], SXs[8];
    __shared__ float sCc[6], sDd[6], sEe[6];

    // ======== Phase A: cooperative parameter trig (once per CTA, not per thread) ========
    if (tid < 10) {
        int l = tid / 5, q = tid % 5;
        M2 g = fuse_zyx(params[l*37 + 3*q], params[l*37 + 3*q + 1], params[l*37 + 3*q + 2]);
        float* gm = GM[tid];
        gm[0] = g.m00.re; gm[1] = g.m00.im;
        gm[2] = g.m01.re; gm[3] = g.m01.im;
        gm[4] = g.m10.re; gm[5] = g.m10.im;
        gm[6] = g.m11.re; gm[7] = g.m11.im;
    } else if (tid < 18) {
        int k = tid - 10;
        int l = k >> 2, kk = k & 3;
        sincosf(0.5f*params[l*37 + 15 + kk], &SXs[k], &CXs[k]);
    } else if (tid >= 32 && tid < 38) {
        int q = tid - 32;
        M2 u0 = fuse_zyx(params[19+3*q],    params[20+3*q],    params[21+3*q]);
        M2 u1 = fuse_zyx(params[37+19+3*q], params[37+20+3*q], params[37+21+3*q]);
        M2 M = mmul(u1, u0);
        float h00 = (M.m00.re*M.m00.re + M.m00.im*M.m00.im)
                  - (M.m10.re*M.m10.re + M.m10.im*M.m10.im);
        float h11 = (M.m01.re*M.m01.re + M.m01.im*M.m01.im)
                  - (M.m11.re*M.m11.re + M.m11.im*M.m11.im);
        float imh01 = (M.m00.re*M.m01.im - M.m00.im*M.m01.re)
                    - (M.m10.re*M.m11.im - M.m10.im*M.m11.re);
        sCc[q] = 0.5f*(h00 + h11);
        sDd[q] = 0.5f*(h00 - h11);
        sEe[q] = imh01;
    }

    // identity columns for U'' build
    #pragma unroll
    for (int r = 0; r < 8; ++r) {
        int i = 8*w + r;
        Sre[i*33 + col] = (i == col) ? 1.f : 0.f;
        Sim[i*33 + col] = 0.f;
    }
    __syncthreads();

    // ======== Phase B: cooperative build of U'' = CRX1*G2*CRX0*G1 ========
    g1q_s<16>(Sre, Sim, col, w, GM[0]); __syncthreads();
    g1q_s< 8>(Sre, Sim, col, w, GM[1]); __syncthreads();
    g1q_s< 4>(Sre, Sim, col, w, GM[2]); __syncthreads();
    g1q_s< 2>(Sre, Sim, col, w, GM[3]); __syncthreads();
    g1q_s< 1>(Sre, Sim, col, w, GM[4]); __syncthreads();
    gcrx_s<16,8>(Sre, Sim, col, w, CXs[0], SXs[0]); __syncthreads();
    gcrx_s< 8,4>(Sre, Sim, col, w, CXs[1], SXs[1]); __syncthreads();
    gcrx_s< 4,2>(Sre, Sim, col, w, CXs[2], SXs[2]); __syncthreads();
    gcrx_s< 2,1>(Sre, Sim, col, w, CXs[3], SXs[3]); __syncthreads();
    g1q_s<16>(Sre, Sim, col, w, GM[5]); __syncthreads();
    g1q_s< 8>(Sre, Sim, col, w, GM[6]); __syncthreads();
    g1q_s< 4>(Sre, Sim, col, w, GM[7]); __syncthreads();
    g1q_s< 2>(Sre, Sim, col, w, GM[8]); __syncthreads();
    g1q_s< 1>(Sre, Sim, col, w, GM[9]); __syncthreads();
    gcrx_s<16,8>(Sre, Sim, col, w, CXs[4], SXs[4]); __syncthreads();
    gcrx_s< 8,4>(Sre, Sim, col, w, CXs[5], SXs[5]); __syncthreads();
    gcrx_s< 4,2>(Sre, Sim, col, w, CXs[6], SXs[6]); __syncthreads();
    gcrx_s< 2,1>(Sre, Sim, col, w, CXs[7], SXs[7]); __syncthreads();

    if (tid < 32) {
        // ======== warp 0: recurrence loop — zero shuffles, 5 REDUX per step ========
        const int lane = tid;

        // read ROW lane of U'', fold embed phase (-i)^popc(col)
        float Rr[32], Ri[32];
        #pragma unroll
        for (int j = 0; j < 32; ++j) {
            float re = Sre[lane*33 + j];
            float im = Sim[lane*33 + j];
            int k = __popc(j) & 3;
            float a, bb;
            if (k == 0)      { a =  re; bb =  im; }
            else if (k == 1) { a =  im; bb = -re; }
            else if (k == 2) { a = -re; bb = -im; }
            else             { a = -im; bb =  re; }
            Rr[j] = a; Ri[j] = bb;
        }

        // half-angles zf_q = z_q/2, replicated on ALL lanes
        float zf0 = 0.5f*hidden[b*NH + 0];
        float zf1 = 0.5f*hidden[b*NH + 1];
        float zf2 = 0.5f*hidden[b*NH + 2];
        float zf3 = 0.5f*hidden[b*NH + 3];
        float zf4 = 0.5f*hidden[b*NH + 4];

        const float SCALE    = 1073741824.0f;          // 2^30
        const float INV2_31  = 4.656612873077393e-10f; // 2^-31 (t*2^-30 * 1/2)

        #pragma unroll 1
        for (int t = 0; t < SEQ; ++t) {
            // ---- local trig of all 5 angles (lane-invariant) ----
            float c0 = __cosf(zf0), s0 = __sinf(zf0);
            float c1 = __cosf(zf1), s1 = __sinf(zf1);
            float c2 = __cosf(zf2), s2 = __sinf(zf2);
            float c3 = __cosf(zf3), s3 = __sinf(zf3);
            float c4 = __cosf(zf4), s4 = __sinf(zf4);

            // ---- g over qubits 0..2 (8), h over qubits 3,4 (4) ----
            float g00 = c0*c1, g01 = c0*s1, g10 = s0*c1, g11 = s0*s1;
            float g0 = g00*c2, g1 = g00*s2, g2 = g01*c2, g3 = g01*s2;
            float g4 = g10*c2, g5 = g10*s2, g6 = g11*c2, g7 = g11*s2;
            float h0 = c3*c4, h1 = c3*s4, h2 = s3*c4, h3 = s3*s4;

            // ---- matvec amp = U''·m, m_j = g[j>>2]·h[j&3]; grouped 4-dots ----
            float aR0 = 0.f, aR1 = 0.f, aI0 = 0.f, aI1 = 0.f;
            #define GRP(k, g, accR, accI)                                   \
            {                                                               \
                float t0 = fmaf(Rr[4*(k)+1], h1, Rr[4*(k)  ] * h0);         \
                float t1 = fmaf(Rr[4*(k)+3], h3, Rr[4*(k)+2] * h2);         \
                accR = fmaf(g, t0 + t1, accR);                              \
                float u0 = fmaf(Ri[4*(k)+1], h1, Ri[4*(k)  ] * h0);         \
                float u1 = fmaf(Ri[4*(k)+3], h3, Ri[4*(k)+2] * h2);         \
                accI = fmaf(g, u0 + u1, accI);                              \
            }
            GRP(0, g0, aR0, aI0) GRP(1, g1, aR1, aI1)
            GRP(2, g2, aR0, aI0) GRP(3, g3, aR1, aI1)
            GRP(4, g4, aR0, aI0) GRP(5, g5, aR1, aI1)
            GRP(6, g6, aR0, aI0) GRP(7, g7, aR1, aI1)
            #undef GRP
            float nar = aR0 + aR1;
            float nai = aI0 + aI1;

            // ---- measure: fixed-point p, 5 REDUX (result on ALL lanes) ----
            float p = fmaf(nar, nar, nai*nai);
            int ip = __float2int_rn(p * SCALE);
            int nip = -ip;
            int t0 = __reduce_add_sync(0xffffffffu, (lane & 16) ? nip : ip);
            int t1 = __reduce_add_sync(0xffffffffu, (lane &  8) ? nip : ip);
            int t2 = __reduce_add_sync(0xffffffffu, (lane &  4) ? nip : ip);
            int t3 = __reduce_add_sync(0xffffffffu, (lane &  2) ? nip : ip);
            int t4 = __reduce_add_sync(0xffffffffu, (lane &  1) ? nip : ip);

            zf0 = (float)t0 * INV2_31;
            zf1 = (float)t1 * INV2_31;
            zf2 = (float)t2 * INV2_31;
            zf3 = (float)t3 * INV2_31;
            zf4 = (float)t4 * INV2_31;
        }

        if (lane < NH) {
            float zz = 2.f*zf0;
            zz = (lane == 1) ? 2.f*zf1 : zz;
            zz = (lane == 2) ? 2.f*zf2 : zz;
            zz = (lane == 3) ? 2.f*zf3 : zz;
            zz = (lane == 4) ? 2.f*zf4 : zz;
            out[BATCH*SEQ*NV + b*NH + lane] = zz;
        }

    } else {
        // ============ warps 1-3: closed-form outputs (C/D/E from SMEM) ============
        const int t = tid - 32;
        if (t >= SEQ) return;

        const int P = b * SEQ + t;
        const float4* x4 = (const float4*)(x + (size_t)P * FEAT);
        float vals[60];
        #pragma unroll
        for (int k = 0; k < 15; k++) {
            float4 v4 = x4[k];
            vals[4*k+0] = v4.x; vals[4*k+1] = v4.y;
            vals[4*k+2] = v4.z; vals[4*k+3] = v4.w;
        }
        float pooled[6];
        #pragma unroll
        for (int v = 0; v < 6; v++) {
            float s = 0.f;
            #pragma unroll
            for (int j = 0; j < 10; j++) s += vals[v*10 + j];
            pooled[v] = 0.1f * s;
        }
        float mn = pooled[0], mx = pooled[0];
        #pragma unroll
        for (int v = 1; v < 6; v++) {
            mn = fminf(mn, pooled[v]);
            mx = fmaxf(mx, pooled[v]);
        }
        float scale = TWO_PI / (mx - mn + 1e-8f);
        #pragma unroll
        for (int v = 0; v < 6; v++) {
            float a = scale * (pooled[v] - mn);
            float sa, ca;
            sincosf(a, &sa, &ca);
            out[(size_t)P*6 + v] = sCc[v] + sDd[v]*ca + sEe[v]*sa;
        }
    }
}

extern "C" void kernel_launch(void* const* d_in, const int* in_sizes, int n_in,
                              void* d_out, int out_size) {
    const float* x      = (const float*)d_in[0];
    const float* hidden = (const float*)d_in[1];
    const float* params = (const float*)d_in[2];
    float* out = (float*)d_out;
    qrnn_kernel<<<BATCH, 128>>>(x, hidden, params, out);
}